// round 4
// baseline (speedup 1.0000x reference)
#include <cuda_runtime.h>

#define TPB 384

constexpr int B_     = 16384;
constexpr int N_     = 70;
constexpr int STEPS_ = 5;
constexpr int BB_    = 16;

constexpr int XPLANE = 568;   // u64 per X s-plane (70*8 + 8 pad)
constexpr int PPLANE = 560;   // u64 per P d-plane

// ---- shared memory layout (float offsets) ----
constexpr int OFF_X   = 0;            // 10 planes * 1136 = 11360
constexpr int OFF_P   = 11360;        // 10 planes * 1120 = 11200
constexpr int OFF_AS  = 22560;        // A chunk, up to 70*36 = 2520
constexpr int OFF_WIN = 25080;        // dup [e][d][s]: 300 u64 = 600
constexpr int OFF_BIN = 25680;        // dup [e][s]: 30 u64 = 60
constexpr int OFF_WR  = 25740;        // dup [j][s]: 200 u64 = 400
constexpr int OFF_WZ  = 26140;        // 400
constexpr int OFF_WH  = 26540;        // 400
constexpr int OFF_BR  = 26940;        // 10 u64 = 20
constexpr int OFF_BZ  = 26960;        // 20
constexpr int OFF_BH  = 26980;        // 20
constexpr int OFF_WO1 = 27000;        // 110
constexpr int OFF_BO1 = 27110;        // 10
constexpr int OFF_WO2 = 27120;        // 10
constexpr int OFF_BO2 = 27130;        // 1
constexpr int SMEM_FLOATS = 27131;    // 108524 B/CTA -> 2 CTAs/SM

typedef unsigned long long u64;

// ---- packed f32x2 helpers ----
__device__ __forceinline__ u64 ffma2(u64 a, u64 b, u64 c) {
    u64 d;
    asm("fma.rn.f32x2 %0, %1, %2, %3;" : "=l"(d) : "l"(a), "l"(b), "l"(c));
    return d;
}
__device__ __forceinline__ u64 mul2(u64 a, u64 b) {
    u64 d;
    asm("mul.rn.f32x2 %0, %1, %2;" : "=l"(d) : "l"(a), "l"(b));
    return d;
}
__device__ __forceinline__ u64 pack2(float x) {
    u64 d;
    asm("mov.b64 %0, {%1, %1};" : "=l"(d) : "f"(x));
    return d;
}
__device__ __forceinline__ u64 packxy(float x, float y) {
    u64 d;
    asm("mov.b64 %0, {%1, %2};" : "=l"(d) : "f"(x), "f"(y));
    return d;
}
__device__ __forceinline__ void unpack2(u64 v, float& x, float& y) {
    asm("mov.b64 {%0, %1}, %2;" : "=f"(x), "=f"(y) : "l"(v));
}

__device__ __forceinline__ float sigf(float x) {
    return __fdividef(1.0f, 1.0f + __expf(-x));
}
__device__ __forceinline__ float tanh_(float x) {
    float e = __expf(-2.0f * x);
    return __fdividef(1.0f - e, 1.0f + e);
}

extern __shared__ float sm[];

// ---- stage A[:, e*70+k0 : +KC] chunk into SMEM (scalar) ----
template <int KC>
__device__ __forceinline__ void stageA(const float* __restrict__ Ag, int e,
                                       int k0, int t) {
#pragma unroll 1
    for (int i = t; i < 70 * KC; i += TPB) {
        int row = i / KC, kk = i - row * KC;
        sm[OFF_AS + i] = Ag[row * 210 + e * 70 + k0 + kk];
    }
}

// ---- GEMM partial: acc += A_chunk(rows ty,ty+24[,ty+48]) @ X[k0 : k0+2*NK2] ----
template <int NK2, int R>
__device__ __forceinline__ void gemm_part(u64 (&acc)[3][5], const u64* xk,
                                          int ty) {
    const u64* As2 = (const u64*)(sm + OFF_AS);
    const u64* ar0 = As2 + ty * NK2;
    const u64* ar1 = As2 + (ty + 24) * NK2;
    const u64* ar2 = As2 + (ty + 48) * NK2;
#pragma unroll 1
    for (int kk = 0; kk < NK2; ++kk) {
        const u64* xr = xk + kk * 16;
        u64 a0 = ar0[kk], a1 = ar1[kk];
        u64 a2 = (R == 3) ? ar2[kk] : 0;
        u64 xE[5], xO[5];
#pragma unroll
        for (int j = 0; j < 5; ++j) {
            xE[j] = xr[j * (2 * XPLANE)];
            xO[j] = xr[8 + j * (2 * XPLANE)];
        }
        float l0, h0, l1, h1, l2, h2;
        unpack2(a0, l0, h0);
        unpack2(a1, l1, h1);
        unpack2(a2, l2, h2);
        {
            u64 p0 = pack2(l0), p1 = pack2(l1);
#pragma unroll
            for (int j = 0; j < 5; ++j) {
                acc[0][j] = ffma2(p0, xE[j], acc[0][j]);
                acc[1][j] = ffma2(p1, xE[j], acc[1][j]);
            }
            if (R == 3) {
                u64 p2 = pack2(l2);
#pragma unroll
                for (int j = 0; j < 5; ++j)
                    acc[2][j] = ffma2(p2, xE[j], acc[2][j]);
            }
        }
        {
            u64 p0 = pack2(h0), p1 = pack2(h1);
#pragma unroll
            for (int j = 0; j < 5; ++j) {
                acc[0][j] = ffma2(p0, xO[j], acc[0][j]);
                acc[1][j] = ffma2(p1, xO[j], acc[1][j]);
            }
            if (R == 3) {
                u64 p2 = pack2(h2);
#pragma unroll
                for (int j = 0; j < 5; ++j)
                    acc[2][j] = ffma2(p2, xO[j], acc[2][j]);
            }
        }
    }
}

__global__ void __launch_bounds__(TPB, 2) ggnn_kernel(
    const float* __restrict__ annotation, const float* __restrict__ Ag,
    const float* __restrict__ W_in, const float* __restrict__ b_in,
    const float* __restrict__ Wr, const float* __restrict__ br,
    const float* __restrict__ Wz, const float* __restrict__ bz,
    const float* __restrict__ Wh, const float* __restrict__ bh,
    const float* __restrict__ Wo1, const float* __restrict__ bo1,
    const float* __restrict__ Wo2, const float* __restrict__ bo2,
    float* __restrict__ out)
{
    const int t  = threadIdx.x;
    const int b0 = blockIdx.x * BB_;

    // ---- stage duplicated weight tables ----
    for (int i = t; i < 300; i += TPB) {          // WIN dup [e][d][s]
        int e = i / 100, r = i - e * 100;
        int d = r / 10, s = r - d * 10;
        float v = W_in[(e * 10 + s) * 10 + d];
        ((float2*)(sm + OFF_WIN))[i] = make_float2(v, v);
    }
    if (t < 30) {                                 // BIN dup [e][s]
        float v = b_in[t];
        ((float2*)(sm + OFF_BIN))[t] = make_float2(v, v);
    }
    for (int i = t; i < 200; i += TPB) {          // W{r,z,h} dup [j][s]
        int j = i / 10, s = i - j * 10;
        float v;
        v = Wr[s * 20 + j]; ((float2*)(sm + OFF_WR))[i] = make_float2(v, v);
        v = Wz[s * 20 + j]; ((float2*)(sm + OFF_WZ))[i] = make_float2(v, v);
        v = Wh[s * 20 + j]; ((float2*)(sm + OFF_WH))[i] = make_float2(v, v);
    }
    if (t < 10) {
        float v;
        v = br[t]; ((float2*)(sm + OFF_BR))[t] = make_float2(v, v);
        v = bz[t]; ((float2*)(sm + OFF_BZ))[t] = make_float2(v, v);
        v = bh[t]; ((float2*)(sm + OFF_BH))[t] = make_float2(v, v);
        sm[OFF_BO1 + t] = bo1[t];
        sm[OFF_WO2 + t] = Wo2[t];
    }
    for (int i = t; i < 110; i += TPB) sm[OFF_WO1 + i] = Wo1[i];
    if (t == 0) sm[OFF_BO2] = bo2[0];

    // ---- prop init: P[0][n*16+bb] = ann, rest 0 ----
    for (int i = t; i < BB_ * N_; i += TPB) {
        int bb = i / N_, n = i - bb * N_;
        float a = annotation[b0 * N_ + i];
        sm[OFF_P + n * 16 + bb] = a;
#pragma unroll
        for (int d = 1; d < 10; ++d) sm[OFF_P + d * 1120 + n * 16 + bb] = 0.0f;
    }
    __syncthreads();

    const int tx  = t & 15;          // column-pair group
    const int ty  = t >> 4;          // row group (0..23)
    const int txh = tx >> 3;         // X plane parity
    const int bpx = tx & 7;          // batch-pair within plane
    const bool r3 = (ty < 22);       // 3 rows vs 2

    u64 acc[3][5];

#pragma unroll 1
    for (int step = 0; step < STEPS_; ++step) {
#pragma unroll
        for (int i = 0; i < 3; ++i)
#pragma unroll
            for (int j = 0; j < 5; ++j) acc[i][j] = 0ull;

#pragma unroll 1
        for (int e = 0; e < 3; ++e) {
            // stage A first half + build X (both write-only, no conflict)
            stageA<36>(Ag, e, 0, t);
            // ---- build X[s][n*16+bb] = ins (batch-paired) ----
#pragma unroll 1
            for (int task = t; task < 560; task += TPB) {
                int n = task >> 3, bbp = task & 7;
                const u64* Pu = (const u64*)(sm + OFF_P) + n * 8 + bbp;
                const u64* Bi = (const u64*)(sm + OFF_BIN) + e * 10;
                u64 a[10];
#pragma unroll
                for (int s = 0; s < 10; ++s) a[s] = Bi[s];
                const ulonglong2* W =
                    (const ulonglong2*)((const u64*)(sm + OFF_WIN) + e * 100);
#pragma unroll
                for (int d = 0; d < 10; ++d) {
                    u64 pv = Pu[d * PPLANE];
#pragma unroll
                    for (int q = 0; q < 5; ++q) {
                        ulonglong2 w = W[d * 5 + q];
                        a[2 * q]     = ffma2(pv, w.x, a[2 * q]);
                        a[2 * q + 1] = ffma2(pv, w.y, a[2 * q + 1]);
                    }
                }
                u64* Xu = (u64*)(sm + OFF_X) + n * 8 + bbp;
#pragma unroll
                for (int s = 0; s < 10; ++s) Xu[s * XPLANE] = a[s];
            }
            __syncthreads();

            const u64* xbase = (const u64*)(sm + OFF_X) + txh * XPLANE + bpx;
            if (r3) gemm_part<18, 3>(acc, xbase, ty);
            else    gemm_part<18, 2>(acc, xbase, ty);
            __syncthreads();

            stageA<34>(Ag, e, 36, t);
            __syncthreads();

            if (r3) gemm_part<17, 3>(acc, xbase + 36 * 8, ty);
            else    gemm_part<17, 2>(acc, xbase + 36 * 8, ty);
            __syncthreads();
        }

        // ---- write a_in into X planes ----
        {
            u64* Xu = (u64*)(sm + OFF_X) + txh * XPLANE + bpx;
#pragma unroll
            for (int i = 0; i < 2; ++i) {
                int row = ty + 24 * i;
#pragma unroll
                for (int j = 0; j < 5; ++j)
                    Xu[j * (2 * XPLANE) + row * 8] = acc[i][j];
            }
            if (r3) {
                int row = ty + 48;
#pragma unroll
                for (int j = 0; j < 5; ++j)
                    Xu[j * (2 * XPLANE) + row * 8] = acc[2][j];
            }
        }
        __syncthreads();

        // ---- gates (batch-paired, no operand packing) ----
#pragma unroll 1
        for (int task = t; task < 560; task += TPB) {
            int n = task >> 3, bbp = task & 7;
            const u64* Xu = (const u64*)(sm + OFF_X) + n * 8 + bbp;
            u64* Pu = (u64*)(sm + OFF_P) + n * 8 + bbp;

            // r gate
            u64 g[10];
#pragma unroll
            for (int s = 0; s < 10; ++s)
                g[s] = ((const u64*)(sm + OFF_BR))[s];
            {
                const ulonglong2* W = (const ulonglong2*)(sm + OFF_WR);
#pragma unroll
                for (int j = 0; j < 10; ++j) {
                    u64 op = Xu[j * XPLANE];
#pragma unroll
                    for (int q = 0; q < 5; ++q) {
                        ulonglong2 w = W[j * 5 + q];
                        g[2 * q]     = ffma2(op, w.x, g[2 * q]);
                        g[2 * q + 1] = ffma2(op, w.y, g[2 * q + 1]);
                    }
                }
#pragma unroll
                for (int j = 0; j < 10; ++j) {
                    u64 op = Pu[j * PPLANE];
#pragma unroll
                    for (int q = 0; q < 5; ++q) {
                        ulonglong2 w = W[(10 + j) * 5 + q];
                        g[2 * q]     = ffma2(op, w.x, g[2 * q]);
                        g[2 * q + 1] = ffma2(op, w.y, g[2 * q + 1]);
                    }
                }
            }
            // rp = sigmoid(r) * prop  (packed)
            u64 rp[10];
#pragma unroll
            for (int s = 0; s < 10; ++s) {
                float x, y;
                unpack2(g[s], x, y);
                rp[s] = mul2(packxy(sigf(x), sigf(y)), Pu[s * PPLANE]);
            }
            // h_hat pre-activation into g
#pragma unroll
            for (int s = 0; s < 10; ++s)
                g[s] = ((const u64*)(sm + OFF_BH))[s];
            {
                const ulonglong2* W = (const ulonglong2*)(sm + OFF_WH);
#pragma unroll
                for (int j = 0; j < 10; ++j) {
                    u64 op = Xu[j * XPLANE];
#pragma unroll
                    for (int q = 0; q < 5; ++q) {
                        ulonglong2 w = W[j * 5 + q];
                        g[2 * q]     = ffma2(op, w.x, g[2 * q]);
                        g[2 * q + 1] = ffma2(op, w.y, g[2 * q + 1]);
                    }
                }
#pragma unroll
                for (int j = 0; j < 10; ++j) {
                    u64 op = rp[j];
#pragma unroll
                    for (int q = 0; q < 5; ++q) {
                        ulonglong2 w = W[(10 + j) * 5 + q];
                        g[2 * q]     = ffma2(op, w.x, g[2 * q]);
                        g[2 * q + 1] = ffma2(op, w.y, g[2 * q + 1]);
                    }
                }
            }
            // g := tanh(g)
#pragma unroll
            for (int s = 0; s < 10; ++s) {
                float x, y;
                unpack2(g[s], x, y);
                g[s] = packxy(tanh_(x), tanh_(y));
            }
            // z gate into rp (registers reused)
#pragma unroll
            for (int s = 0; s < 10; ++s)
                rp[s] = ((const u64*)(sm + OFF_BZ))[s];
            {
                const ulonglong2* W = (const ulonglong2*)(sm + OFF_WZ);
#pragma unroll
                for (int j = 0; j < 10; ++j) {
                    u64 op = Xu[j * XPLANE];
#pragma unroll
                    for (int q = 0; q < 5; ++q) {
                        ulonglong2 w = W[j * 5 + q];
                        rp[2 * q]     = ffma2(op, w.x, rp[2 * q]);
                        rp[2 * q + 1] = ffma2(op, w.y, rp[2 * q + 1]);
                    }
                }
#pragma unroll
                for (int j = 0; j < 10; ++j) {
                    u64 op = Pu[j * PPLANE];
#pragma unroll
                    for (int q = 0; q < 5; ++q) {
                        ulonglong2 w = W[(10 + j) * 5 + q];
                        rp[2 * q]     = ffma2(op, w.x, rp[2 * q]);
                        rp[2 * q + 1] = ffma2(op, w.y, rp[2 * q + 1]);
                    }
                }
            }
            // update: prop = prop + z*(h - prop)
#pragma unroll
            for (int s = 0; s < 10; ++s) {
                float zl, zh, hl, hh, pl, ph;
                unpack2(rp[s], zl, zh);
                unpack2(g[s], hl, hh);
                unpack2(Pu[s * PPLANE], pl, ph);
                zl = sigf(zl); zh = sigf(zh);
                float ol = pl + zl * (hl - pl);
                float oh = ph + zh * (hh - ph);
                Pu[s * PPLANE] = packxy(ol, oh);
            }
        }
        __syncthreads();
    }

    // ---- output ----
#pragma unroll 1
    for (int i = t; i < BB_ * N_; i += TPB) {
        int bb = i / N_, n = i - bb * N_;
        float an = annotation[b0 * N_ + i];
        float pv[10];
#pragma unroll
        for (int j = 0; j < 10; ++j)
            pv[j] = sm[OFF_P + j * 1120 + n * 16 + bb];
        float o = sm[OFF_BO2];
#pragma unroll 2
        for (int s = 0; s < 10; ++s) {
            float a0 = sm[OFF_BO1 + s];
#pragma unroll
            for (int j = 0; j < 10; ++j)
                a0 += pv[j] * sm[OFF_WO1 + s * 11 + j];
            a0 += an * sm[OFF_WO1 + s * 11 + 10];
            o += tanh_(a0) * sm[OFF_WO2 + s];
        }
        out[b0 * N_ + i] = o;
    }
}

extern "C" void kernel_launch(void* const* d_in, const int* in_sizes, int n_in,
                              void* d_out, int out_size) {
    const float* annotation = (const float*)d_in[0];
    const float* A    = (const float*)d_in[1];
    const float* W_in = (const float*)d_in[2];
    const float* b_in = (const float*)d_in[3];
    const float* Wr   = (const float*)d_in[4];
    const float* br   = (const float*)d_in[5];
    const float* Wz   = (const float*)d_in[6];
    const float* bz   = (const float*)d_in[7];
    const float* Wh   = (const float*)d_in[8];
    const float* bh   = (const float*)d_in[9];
    const float* Wo1  = (const float*)d_in[10];
    const float* bo1  = (const float*)d_in[11];
    const float* Wo2  = (const float*)d_in[12];
    const float* bo2  = (const float*)d_in[13];
    float* out = (float*)d_out;

    const int smem_bytes = SMEM_FLOATS * (int)sizeof(float);
    cudaFuncSetAttribute(ggnn_kernel,
                         cudaFuncAttributeMaxDynamicSharedMemorySize, smem_bytes);
    ggnn_kernel<<<B_ / BB_, TPB, smem_bytes>>>(
        annotation, A, W_in, b_in, Wr, br, Wz, bz, Wh, bh,
        Wo1, bo1, Wo2, bo2, out);
}

// round 5
// speedup vs baseline: 1.1770x; 1.1770x over previous
#include <cuda_runtime.h>

#define TPB 256

constexpr int B_     = 16384;
constexpr int N_     = 70;
constexpr int STEPS_ = 5;
constexpr int BB_    = 16;

constexpr int XPLANE = 568;   // u64 per X s-plane (70*8 + 8 pad -> +16 bank shift)
constexpr int PPLANE = 560;   // u64 per P d-plane

// ---- shared memory layout (float offsets) ----
constexpr int OFF_X   = 0;            // 10 planes * 1136 = 11360
constexpr int OFF_P   = 11360;        // 10 planes * 1120 = 11200
constexpr int OFF_AS  = 22560;        // A half-chunk, up to 70*36 = 2520
constexpr int OFF_WIN = 25080;        // dup [e][d][s]: 300 u64 = 600
constexpr int OFF_BIN = 25680;        // dup [e][s]: 30 u64 = 60
constexpr int OFF_WR  = 25740;        // dup [j][s]: 200 u64 = 400
constexpr int OFF_WZ  = 26140;        // 400
constexpr int OFF_WH  = 26540;        // 400
constexpr int OFF_BR  = 26940;        // 10 u64 = 20
constexpr int OFF_BZ  = 26960;        // 20
constexpr int OFF_BH  = 26980;        // 20
constexpr int OFF_WO1 = 27000;        // 110
constexpr int OFF_BO1 = 27110;        // 10
constexpr int OFF_WO2 = 27120;        // 10
constexpr int OFF_BO2 = 27130;        // 1
constexpr int SMEM_FLOATS = 27131;    // 108524 B/CTA -> 2 CTAs/SM

typedef unsigned long long u64;

// ---- packed f32x2 helpers ----
__device__ __forceinline__ u64 ffma2(u64 a, u64 b, u64 c) {
    u64 d;
    asm("fma.rn.f32x2 %0, %1, %2, %3;" : "=l"(d) : "l"(a), "l"(b), "l"(c));
    return d;
}
__device__ __forceinline__ u64 mul2(u64 a, u64 b) {
    u64 d;
    asm("mul.rn.f32x2 %0, %1, %2;" : "=l"(d) : "l"(a), "l"(b));
    return d;
}
__device__ __forceinline__ u64 pack2(float x) {
    u64 d;
    asm("mov.b64 %0, {%1, %1};" : "=l"(d) : "f"(x));
    return d;
}
__device__ __forceinline__ u64 packxy(float x, float y) {
    u64 d;
    asm("mov.b64 %0, {%1, %2};" : "=l"(d) : "f"(x), "f"(y));
    return d;
}
__device__ __forceinline__ void unpack2(u64 v, float& x, float& y) {
    asm("mov.b64 {%0, %1}, %2;" : "=f"(x), "=f"(y) : "l"(v));
}

__device__ __forceinline__ float sigf(float x) {
    return __fdividef(1.0f, 1.0f + __expf(-x));
}
__device__ __forceinline__ float tanh_(float x) {
    float e = __expf(-2.0f * x);
    return __fdividef(1.0f - e, 1.0f + e);
}

extern __shared__ float sm[];

// ---- stage A[:, e*70+k0 : +KC] chunk into SMEM (scalar, row-major) ----
template <int KC>
__device__ __forceinline__ void stageA(const float* __restrict__ Ag, int e,
                                       int k0, int t) {
#pragma unroll 1
    for (int i = t; i < 70 * KC; i += TPB) {
        int row = i / KC, kk = i - row * KC;
        sm[OFF_AS + i] = Ag[row * 210 + e * 70 + k0 + kk];
    }
}

// ---- GEMM partial: rows {ty,ty+16,ty+32,ty+48[,64+ty]}, k2 in [0,NK2) ----
template <int NK2, int R>
__device__ __forceinline__ void gemm_part(u64 (&acc)[5][5], const u64* xk,
                                          int ty) {
    const u64* As2 = (const u64*)(sm + OFF_AS);
    const u64* ar0 = As2 + (ty +  0) * NK2;
    const u64* ar1 = As2 + (ty + 16) * NK2;
    const u64* ar2 = As2 + (ty + 32) * NK2;
    const u64* ar3 = As2 + (ty + 48) * NK2;
    const u64* ar4 = As2 + (64 + ty) * NK2;
#pragma unroll 1
    for (int kk = 0; kk < NK2; ++kk) {
        const u64* xr = xk + kk * 16;
        u64 aw0 = ar0[kk], aw1 = ar1[kk], aw2 = ar2[kk], aw3 = ar3[kk];
        u64 aw4 = (R == 5) ? ar4[kk] : 0;
        u64 xE[5], xO[5];
#pragma unroll
        for (int j = 0; j < 5; ++j) {
            xE[j] = xr[j * (2 * XPLANE)];
            xO[j] = xr[8 + j * (2 * XPLANE)];
        }
        float l0, h0, l1, h1, l2, h2, l3, h3, l4, h4;
        unpack2(aw0, l0, h0);
        unpack2(aw1, l1, h1);
        unpack2(aw2, l2, h2);
        unpack2(aw3, l3, h3);
        unpack2(aw4, l4, h4);
        {
            u64 p0 = pack2(l0), p1 = pack2(l1), p2 = pack2(l2), p3 = pack2(l3);
#pragma unroll
            for (int j = 0; j < 5; ++j) {
                acc[0][j] = ffma2(p0, xE[j], acc[0][j]);
                acc[1][j] = ffma2(p1, xE[j], acc[1][j]);
                acc[2][j] = ffma2(p2, xE[j], acc[2][j]);
                acc[3][j] = ffma2(p3, xE[j], acc[3][j]);
            }
            if (R == 5) {
                u64 p4 = pack2(l4);
#pragma unroll
                for (int j = 0; j < 5; ++j)
                    acc[4][j] = ffma2(p4, xE[j], acc[4][j]);
            }
        }
        {
            u64 p0 = pack2(h0), p1 = pack2(h1), p2 = pack2(h2), p3 = pack2(h3);
#pragma unroll
            for (int j = 0; j < 5; ++j) {
                acc[0][j] = ffma2(p0, xO[j], acc[0][j]);
                acc[1][j] = ffma2(p1, xO[j], acc[1][j]);
                acc[2][j] = ffma2(p2, xO[j], acc[2][j]);
                acc[3][j] = ffma2(p3, xO[j], acc[3][j]);
            }
            if (R == 5) {
                u64 p4 = pack2(h4);
#pragma unroll
                for (int j = 0; j < 5; ++j)
                    acc[4][j] = ffma2(p4, xO[j], acc[4][j]);
            }
        }
    }
}

__global__ void __launch_bounds__(TPB, 2) ggnn_kernel(
    const float* __restrict__ annotation, const float* __restrict__ Ag,
    const float* __restrict__ W_in, const float* __restrict__ b_in,
    const float* __restrict__ Wr, const float* __restrict__ br,
    const float* __restrict__ Wz, const float* __restrict__ bz,
    const float* __restrict__ Wh, const float* __restrict__ bh,
    const float* __restrict__ Wo1, const float* __restrict__ bo1,
    const float* __restrict__ Wo2, const float* __restrict__ bo2,
    float* __restrict__ out)
{
    const int t  = threadIdx.x;
    const int b0 = blockIdx.x * BB_;

    // ---- stage duplicated weight tables ----
    for (int i = t; i < 300; i += TPB) {          // WIN dup [e][d][s]
        int e = i / 100, r = i - e * 100;
        int d = r / 10, s = r - d * 10;
        float v = W_in[(e * 10 + s) * 10 + d];
        ((float2*)(sm + OFF_WIN))[i] = make_float2(v, v);
    }
    if (t < 30) {                                 // BIN dup [e][s]
        float v = b_in[t];
        ((float2*)(sm + OFF_BIN))[t] = make_float2(v, v);
    }
    for (int i = t; i < 200; i += TPB) {          // W{r,z,h} dup [j][s]
        int j = i / 10, s = i - j * 10;
        float v;
        v = Wr[s * 20 + j]; ((float2*)(sm + OFF_WR))[i] = make_float2(v, v);
        v = Wz[s * 20 + j]; ((float2*)(sm + OFF_WZ))[i] = make_float2(v, v);
        v = Wh[s * 20 + j]; ((float2*)(sm + OFF_WH))[i] = make_float2(v, v);
    }
    if (t < 10) {
        float v;
        v = br[t]; ((float2*)(sm + OFF_BR))[t] = make_float2(v, v);
        v = bz[t]; ((float2*)(sm + OFF_BZ))[t] = make_float2(v, v);
        v = bh[t]; ((float2*)(sm + OFF_BH))[t] = make_float2(v, v);
        sm[OFF_BO1 + t] = bo1[t];
        sm[OFF_WO2 + t] = Wo2[t];
    }
    for (int i = t; i < 110; i += TPB) sm[OFF_WO1 + i] = Wo1[i];
    if (t == 0) sm[OFF_BO2] = bo2[0];

    // ---- prop init: P[0][n*16+bb] = ann, rest 0 ----
    for (int i = t; i < BB_ * N_; i += TPB) {
        int bb = i / N_, n = i - bb * N_;
        float a = annotation[b0 * N_ + i];
        sm[OFF_P + n * 16 + bb] = a;
#pragma unroll
        for (int d = 1; d < 10; ++d) sm[OFF_P + d * 1120 + n * 16 + bb] = 0.0f;
    }
    __syncthreads();

    const int tx  = t & 15;          // column group
    const int ty  = t >> 4;          // row group (0..15)
    const int txh = tx >> 3;         // X plane parity
    const int bpx = tx & 7;          // batch-pair within plane
    const bool r5 = (ty < 6);        // 5th GEMM row valid

    u64 acc[5][5];

#pragma unroll 1
    for (int step = 0; step < STEPS_; ++step) {
#pragma unroll
        for (int i = 0; i < 5; ++i)
#pragma unroll
            for (int j = 0; j < 5; ++j) acc[i][j] = 0ull;

#pragma unroll 1
        for (int e = 0; e < 3; ++e) {
            // stage A first half + build X (both write-only, disjoint)
            stageA<36>(Ag, e, 0, t);
            // ---- build X[s][n*8+bbp] = ins (batch-paired, MOV-free) ----
#pragma unroll 1
            for (int task = t; task < 560; task += TPB) {
                int n = task >> 3, bbp = task & 7;
                const u64* Pu = (const u64*)(sm + OFF_P) + n * 8 + bbp;
                const u64* Bi = (const u64*)(sm + OFF_BIN) + e * 10;
                u64 a[10];
#pragma unroll
                for (int s = 0; s < 10; ++s) a[s] = Bi[s];
                const ulonglong2* W =
                    (const ulonglong2*)((const u64*)(sm + OFF_WIN) + e * 100);
#pragma unroll
                for (int d = 0; d < 10; ++d) {
                    u64 pv = Pu[d * PPLANE];
#pragma unroll
                    for (int q = 0; q < 5; ++q) {
                        ulonglong2 w = W[d * 5 + q];
                        a[2 * q]     = ffma2(pv, w.x, a[2 * q]);
                        a[2 * q + 1] = ffma2(pv, w.y, a[2 * q + 1]);
                    }
                }
                u64* Xu = (u64*)(sm + OFF_X) + n * 8 + bbp;
#pragma unroll
                for (int s = 0; s < 10; ++s) Xu[s * XPLANE] = a[s];
            }
            __syncthreads();

            const u64* xbase = (const u64*)(sm + OFF_X) + txh * XPLANE + bpx;
            if (r5) gemm_part<18, 5>(acc, xbase, ty);
            else    gemm_part<18, 4>(acc, xbase, ty);
            __syncthreads();

            stageA<34>(Ag, e, 36, t);
            __syncthreads();

            if (r5) gemm_part<17, 5>(acc, xbase + 36 * 8, ty);
            else    gemm_part<17, 4>(acc, xbase + 36 * 8, ty);
            __syncthreads();
        }

        // ---- write a_in into X planes ----
        {
            u64* Xu = (u64*)(sm + OFF_X) + txh * XPLANE + bpx;
#pragma unroll
            for (int i = 0; i < 4; ++i) {
                int row = ty + 16 * i;
#pragma unroll
                for (int j = 0; j < 5; ++j)
                    Xu[j * (2 * XPLANE) + row * 8] = acc[i][j];
            }
            if (r5) {
                int row = 64 + ty;
#pragma unroll
                for (int j = 0; j < 5; ++j)
                    Xu[j * (2 * XPLANE) + row * 8] = acc[4][j];
            }
        }
        __syncthreads();

        // ---- gates (batch-paired, no operand packing) ----
#pragma unroll 1
        for (int task = t; task < 560; task += TPB) {
            int n = task >> 3, bbp = task & 7;
            const u64* Xu = (const u64*)(sm + OFF_X) + n * 8 + bbp;
            u64* Pu = (u64*)(sm + OFF_P) + n * 8 + bbp;

            // r gate
            u64 g[10];
#pragma unroll
            for (int s = 0; s < 10; ++s)
                g[s] = ((const u64*)(sm + OFF_BR))[s];
            {
                const ulonglong2* W = (const ulonglong2*)(sm + OFF_WR);
#pragma unroll
                for (int j = 0; j < 10; ++j) {
                    u64 op = Xu[j * XPLANE];
#pragma unroll
                    for (int q = 0; q < 5; ++q) {
                        ulonglong2 w = W[j * 5 + q];
                        g[2 * q]     = ffma2(op, w.x, g[2 * q]);
                        g[2 * q + 1] = ffma2(op, w.y, g[2 * q + 1]);
                    }
                }
#pragma unroll
                for (int j = 0; j < 10; ++j) {
                    u64 op = Pu[j * PPLANE];
#pragma unroll
                    for (int q = 0; q < 5; ++q) {
                        ulonglong2 w = W[(10 + j) * 5 + q];
                        g[2 * q]     = ffma2(op, w.x, g[2 * q]);
                        g[2 * q + 1] = ffma2(op, w.y, g[2 * q + 1]);
                    }
                }
            }
            // rp = sigmoid(r) * prop
            u64 rp[10];
#pragma unroll
            for (int s = 0; s < 10; ++s) {
                float x, y;
                unpack2(g[s], x, y);
                rp[s] = mul2(packxy(sigf(x), sigf(y)), Pu[s * PPLANE]);
            }
            // h_hat pre-activation into g
#pragma unroll
            for (int s = 0; s < 10; ++s)
                g[s] = ((const u64*)(sm + OFF_BH))[s];
            {
                const ulonglong2* W = (const ulonglong2*)(sm + OFF_WH);
#pragma unroll
                for (int j = 0; j < 10; ++j) {
                    u64 op = Xu[j * XPLANE];
#pragma unroll
                    for (int q = 0; q < 5; ++q) {
                        ulonglong2 w = W[j * 5 + q];
                        g[2 * q]     = ffma2(op, w.x, g[2 * q]);
                        g[2 * q + 1] = ffma2(op, w.y, g[2 * q + 1]);
                    }
                }
#pragma unroll
                for (int j = 0; j < 10; ++j) {
                    u64 op = rp[j];
#pragma unroll
                    for (int q = 0; q < 5; ++q) {
                        ulonglong2 w = W[(10 + j) * 5 + q];
                        g[2 * q]     = ffma2(op, w.x, g[2 * q]);
                        g[2 * q + 1] = ffma2(op, w.y, g[2 * q + 1]);
                    }
                }
            }
            // g := tanh(g)
#pragma unroll
            for (int s = 0; s < 10; ++s) {
                float x, y;
                unpack2(g[s], x, y);
                g[s] = packxy(tanh_(x), tanh_(y));
            }
            // z gate into rp (registers reused)
#pragma unroll
            for (int s = 0; s < 10; ++s)
                rp[s] = ((const u64*)(sm + OFF_BZ))[s];
            {
                const ulonglong2* W = (const ulonglong2*)(sm + OFF_WZ);
#pragma unroll
                for (int j = 0; j < 10; ++j) {
                    u64 op = Xu[j * XPLANE];
#pragma unroll
                    for (int q = 0; q < 5; ++q) {
                        ulonglong2 w = W[j * 5 + q];
                        rp[2 * q]     = ffma2(op, w.x, rp[2 * q]);
                        rp[2 * q + 1] = ffma2(op, w.y, rp[2 * q + 1]);
                    }
                }
#pragma unroll
                for (int j = 0; j < 10; ++j) {
                    u64 op = Pu[j * PPLANE];
#pragma unroll
                    for (int q = 0; q < 5; ++q) {
                        ulonglong2 w = W[(10 + j) * 5 + q];
                        rp[2 * q]     = ffma2(op, w.x, rp[2 * q]);
                        rp[2 * q + 1] = ffma2(op, w.y, rp[2 * q + 1]);
                    }
                }
            }
            // update: prop = prop + z*(h - prop)
#pragma unroll
            for (int s = 0; s < 10; ++s) {
                float zl, zh, hl, hh, pl, ph;
                unpack2(rp[s], zl, zh);
                unpack2(g[s], hl, hh);
                unpack2(Pu[s * PPLANE], pl, ph);
                zl = sigf(zl); zh = sigf(zh);
                float ol = pl + zl * (hl - pl);
                float oh = ph + zh * (hh - ph);
                Pu[s * PPLANE] = packxy(ol, oh);
            }
        }
        __syncthreads();
    }

    // ---- output ----
#pragma unroll 1
    for (int i = t; i < BB_ * N_; i += TPB) {
        int bb = i / N_, n = i - bb * N_;
        float an = annotation[b0 * N_ + i];
        float pv[10];
#pragma unroll
        for (int j = 0; j < 10; ++j)
            pv[j] = sm[OFF_P + j * 1120 + n * 16 + bb];
        float o = sm[OFF_BO2];
#pragma unroll 2
        for (int s = 0; s < 10; ++s) {
            float a0 = sm[OFF_BO1 + s];
#pragma unroll
            for (int j = 0; j < 10; ++j)
                a0 += pv[j] * sm[OFF_WO1 + s * 11 + j];
            a0 += an * sm[OFF_WO1 + s * 11 + 10];
            o += tanh_(a0) * sm[OFF_WO2 + s];
        }
        out[b0 * N_ + i] = o;
    }
}

extern "C" void kernel_launch(void* const* d_in, const int* in_sizes, int n_in,
                              void* d_out, int out_size) {
    const float* annotation = (const float*)d_in[0];
    const float* A    = (const float*)d_in[1];
    const float* W_in = (const float*)d_in[2];
    const float* b_in = (const float*)d_in[3];
    const float* Wr   = (const float*)d_in[4];
    const float* br   = (const float*)d_in[5];
    const float* Wz   = (const float*)d_in[6];
    const float* bz   = (const float*)d_in[7];
    const float* Wh   = (const float*)d_in[8];
    const float* bh   = (const float*)d_in[9];
    const float* Wo1  = (const float*)d_in[10];
    const float* bo1  = (const float*)d_in[11];
    const float* Wo2  = (const float*)d_in[12];
    const float* bo2  = (const float*)d_in[13];
    float* out = (float*)d_out;

    const int smem_bytes = SMEM_FLOATS * (int)sizeof(float);
    cudaFuncSetAttribute(ggnn_kernel,
                         cudaFuncAttributeMaxDynamicSharedMemorySize, smem_bytes);
    ggnn_kernel<<<B_ / BB_, TPB, smem_bytes>>>(
        annotation, A, W_in, b_in, Wr, br, Wz, bz, Wh, bh,
        Wo1, bo1, Wo2, bo2, out);
}